// round 9
// baseline (speedup 1.0000x reference)
#include <cuda_runtime.h>
#include <cstdint>

#define P_  128
#define D_  128
#define R_  16384
#define E_  131072
#define T_  1024
#define F_  513
#define FP_ 520     // padded row stride in float2 (16B-aligned rows)
#define KT_ 32      // k-chunk for GEMM

// ---------------- scratch (static device allocations; no cudaMalloc) ----------
static __device__ __align__(16) float2 g_bufA[R_*FP_ + 256];   // r_k
static __device__ __align__(16) float2 g_bufB[R_*FP_ + 256];   // prop * (K r)
static __device__ __align__(16) float  g_K[P_*D_*D_];          // [p][e][d]
static __device__ __align__(16) int g_rowptr[R_+4];
static __device__ __align__(16) int g_rowcnt[R_];
static __device__ int    g_cols[E_];
static __device__ float  g_vals[E_];
static __device__ float  g_echo[2*F_];
static __device__ float  g_time[T_];

// ---------------- constants matching reference fp32 rounding ------------------
__device__ __forceinline__ float c_s32()  { return (float)(16000.0/343.0); }                 // SR/C
__device__ __forceinline__ float c_c32()  { return (float)(-2.0*3.14159265358979323846/1024.0); }
__device__ __forceinline__ float c_kdec() { return (float)(-6.907755278982137/343.0 - 0.001); }
#define LOG_GAMMA_F (-6.907755278982137f)

// sin/cos of x (|x| up to ~5000) with 2-term Cody-Waite reduction mod 2pi.
__device__ __forceinline__ void sc_big(float x, float& s, float& c) {
    float k = rintf(x * 0.15915494309189535f);
    float r = fmaf(k, -6.28125f, x);                  // exact (k<2^10, 9-bit C1)
    r = fmaf(k, -1.9353071795864769e-3f, r);
    __sincosf(r, &s, &c);
}

// packed f32x2 helpers
__device__ __forceinline__ unsigned long long pk2(float k) {
    unsigned long long r;
    asm("mov.b64 %0, {%1, %1};" : "=l"(r) : "f"(k));
    return r;
}
__device__ __forceinline__ unsigned long long fma2(unsigned long long a, unsigned long long b,
                                                   unsigned long long c) {
    unsigned long long d;
    asm("fma.rn.f32x2 %0, %1, %2, %3;" : "=l"(d) : "l"(a), "l"(b), "l"(c));
    return d;
}
__device__ __forceinline__ float lo32(unsigned long long v) { return __uint_as_float((unsigned)(v & 0xffffffffull)); }
__device__ __forceinline__ float hi32(unsigned long long v) { return __uint_as_float((unsigned)(v >> 32)); }

// ---------------- setup: build K, zero echo/time/rowcnt (fused) ---------------
__global__ void k_buildKzero(const float* __restrict__ basis, const float* __restrict__ absorb,
                             const float* __restrict__ scat, const int* __restrict__ obj) {
    int idx = blockIdx.x * blockDim.x + threadIdx.x;
    if (idx < 2*F_) g_echo[idx] = 0.0f;
    if (idx < T_)   g_time[idx] = 0.0f;
    if (idx < R_)   g_rowcnt[idx] = 0;
    if (idx >= P_*D_*D_) return;
    int p = idx / (D_*D_);
    int rem = idx - p*D_*D_;
    int e = rem / D_;
    int d = rem - e*D_;
    int o = obj[p];
    float refl = 1.0f - absorb[o];
    float c0 = refl * scat[o];
    float c1 = refl * (1.0f - scat[o]);
    g_K[idx] = c0 * basis[d*D_ + e] + c1 * basis[D_*D_ + d*D_ + e];
}

__global__ void k_hist(const int* __restrict__ gkr) {
    int e = blockIdx.x * blockDim.x + threadIdx.x;
    if (e < E_) atomicAdd(&g_rowcnt[gkr[e]], 1);
}

// single block, 1024 threads, 16 values each: int4 loads + shuffle scan
__global__ void __launch_bounds__(1024) k_scan() {
    __shared__ int wsum[32];
    int t = threadIdx.x, lane = t & 31, wid = t >> 5;
    int4 v[4];
    const int4* src = (const int4*)g_rowcnt;
#pragma unroll
    for (int i = 0; i < 4; i++) v[i] = src[t*4 + i];
    const int* x = (const int*)v;
    int loc[16], sum = 0;
#pragma unroll
    for (int i = 0; i < 16; i++) { loc[i] = sum; sum += x[i]; }
    int incl = sum;
#pragma unroll
    for (int off = 1; off < 32; off <<= 1) {
        int n = __shfl_up_sync(0xffffffffu, incl, off);
        if (lane >= off) incl += n;
    }
    if (lane == 31) wsum[wid] = incl;
    __syncthreads();
    if (wid == 0) {
        int ws = wsum[lane];
#pragma unroll
        for (int off = 1; off < 32; off <<= 1) {
            int n = __shfl_up_sync(0xffffffffu, ws, off);
            if (lane >= off) ws += n;
        }
        wsum[lane] = ws;
    }
    __syncthreads();
    int off0 = (wid > 0 ? wsum[wid-1] : 0) + (incl - sum);
    int4 o[4];
    int* op = (int*)o;
#pragma unroll
    for (int i = 0; i < 16; i++) op[i] = off0 + loc[i];
    int4* dst = (int4*)g_rowptr;
    int4* cz  = (int4*)g_rowcnt;
    int4 z = make_int4(0,0,0,0);
#pragma unroll
    for (int i = 0; i < 4; i++) { dst[t*4 + i] = o[i]; cz[t*4 + i] = z; }
    if (t == 1023) g_rowptr[R_] = wsum[31];
}

__global__ void k_scatter(const int* __restrict__ gkr, const int* __restrict__ gkc,
                          const float* __restrict__ gkv) {
    int e = blockIdx.x * blockDim.x + threadIdx.x;
    if (e >= E_) return;
    int r = gkr[e];
    int pos = g_rowptr[r] + atomicAdd(&g_rowcnt[r], 1);
    g_cols[pos] = gkc[e];
    g_vals[pos] = gkv[e];
}

// ---------------- rad: bufA = rad, echo += w_rec*pf_rec*rad -------------------
__global__ void __launch_bounds__(256) k_rad(const float* __restrict__ rpos,
                                             const float* __restrict__ spos,
                                             const float* __restrict__ rcpos) {
    __shared__ __align__(16) float2 esh[8][520];
    int w = threadIdx.x >> 5, lane = threadIdx.x & 31;
    int row = blockIdx.x * 8 + w;

    float px = rpos[3*row+0], py = rpos[3*row+1], pz = rpos[3*row+2];
    float dx = px - spos[0], dy = py - spos[1], dz = pz - spos[2];
    float ds = sqrtf(dx*dx + dy*dy + dz*dz);
    float bs = c_c32() * (ds * c_s32());
    float amp = __expf(c_kdec() * ds) / (ds*ds + 0.001f);

    float rx = px - rcpos[0], ry = py - rcpos[1], rz = pz - rcpos[2];
    float dr = sqrtf(rx*rx + ry*ry + rz*rz);
    float br = c_c32() * (dr * c_s32());
    float wamp = __expf(c_kdec() * dr) / (dr*dr + 0.001f);

#pragma unroll
    for (int k = 0; k < 16; k++) {
        int f = k*32 + lane;
        float s1, c1; sc_big(bs * (float)f, s1, c1);
        float2 rad = make_float2(amp * c1, amp * s1);
        g_bufA[(size_t)row*FP_ + f] = rad;
        float s2, c2; sc_big(br * (float)f, s2, c2);
        esh[w][f] = make_float2(wamp * (c2*rad.x - s2*rad.y), wamp * (c2*rad.y + s2*rad.x));
    }
    if (lane == 0) {
        float s1, c1; sc_big(bs * 512.0f, s1, c1);
        float2 rad = make_float2(amp * c1, amp * s1);
        g_bufA[(size_t)row*FP_ + 512] = rad;
        float s2, c2; sc_big(br * 512.0f, s2, c2);
        esh[w][512] = make_float2(wamp * (c2*rad.x - s2*rad.y), wamp * (c2*rad.y + s2*rad.x));
    }
    __syncthreads();
    for (int f = threadIdx.x; f < F_; f += 256) {
        float sr = 0.0f, si = 0.0f;
#pragma unroll
        for (int ww = 0; ww < 8; ww++) { sr += esh[ww][f].x; si += esh[ww][f].y; }
        atomicAdd(&g_echo[2*f  ], sr);
        atomicAdd(&g_echo[2*f+1], si);
    }
}

// ---------------- GEMM: bufB = prop * (K_p @ bufA), packed f32x2 --------------
// grid (P_, 16): block tile 128d x 32f. Warp w owns f-group w*4..w*4+3 (X is a
// 32B uniform broadcast per warp per kk); the 32 lanes split the 128 d-rows
// (K = one conflict-free LDS.128 per lane). Thread tile 4d x 4f.
// 16 acc regs (u64) -> ~80 regs total -> 3 blocks/SM = 24 warps (occ 37.5%).
__global__ void __launch_bounds__(256, 3) k_gemm(const float* __restrict__ avg_dist) {
    __shared__ float  Ks[KT_][128];      // [e][d]
    __shared__ float2 Xs[KT_][32];       // [e][f]  (32 float2 = 16 float4 per row)
    int p  = blockIdx.x;
    int ft = blockIdx.y;
    int tid = threadIdx.x;
    int w = tid >> 5, lane = tid & 31;
    int f0 = ft * 32;

    unsigned long long acc[16];          // [4 d][4 f]
#pragma unroll
    for (int i = 0; i < 16; i++) acc[i] = 0ull;

    const float*  Kp    = g_K + (size_t)p * D_ * D_;
    const float2* xbase = g_bufA + (size_t)(p*128) * FP_ + f0;

    for (int c = 0; c < 128; c += KT_) {
        // K chunk: 4096 floats = 1024 float4; 256 threads -> 4 each (linear)
        {
            const float4* src = (const float4*)(Kp + c*128);
            float4* dst = (float4*)&Ks[0][0];
#pragma unroll
            for (int i = 0; i < 4; i++) dst[tid + 256*i] = src[tid + 256*i];
        }
        // X chunk: 32 rows x 16 float4 = 512 float4 -> 2 each
#pragma unroll
        for (int i = 0; i < 2; i++) {
            int lin = tid + 256*i;
            int kk = lin >> 4, c4 = lin & 15;
            const float4* s = (const float4*)(xbase + (size_t)(c + kk) * FP_);
            ((float4*)&Xs[kk][0])[c4] = s[c4];
        }
        __syncthreads();
#pragma unroll 4
        for (int kk = 0; kk < KT_; kk++) {
            float4 ka = *(const float4*)&Ks[kk][lane*4];            // per-lane, conflict-free
            const ulonglong2* xp = (const ulonglong2*)&Xs[kk][w*4]; // warp-uniform broadcast
            ulonglong2 x01 = xp[0], x23 = xp[1];
            unsigned long long xv[4] = {x01.x, x01.y, x23.x, x23.y};
            unsigned long long kp[4] = {pk2(ka.x), pk2(ka.y), pk2(ka.z), pk2(ka.w)};
#pragma unroll
            for (int i = 0; i < 4; i++)
#pragma unroll
                for (int j = 0; j < 4; j++)
                    acc[i*4 + j] = fma2(kp[i], xv[j], acc[i*4 + j]);
        }
        __syncthreads();
    }

    int rowb = p*128 + lane*4;
#pragma unroll
    for (int i = 0; i < 4; i++) {
        int row = rowb + i;
        float dist = avg_dist[row];
        float b = c_c32() * (dist * c_s32());
        float dec = __expf(c_kdec() * dist);
        float2* outp = g_bufB + (size_t)row*FP_ + f0 + w*4;
#pragma unroll
        for (int j = 0; j < 4; j += 2) {
            int f = f0 + w*4 + j;
            float ar0 = lo32(acc[i*4 + j]),   ai0 = hi32(acc[i*4 + j]);
            float ar1 = lo32(acc[i*4 + j+1]), ai1 = hi32(acc[i*4 + j+1]);
            float ss0, cc0; sc_big(b * (float)f, ss0, cc0);
            float ss1, cc1; sc_big(b * (float)(f+1), ss1, cc1);
            float pr0 = dec * cc0, pi0 = dec * ss0;
            float pr1 = dec * cc1, pi1 = dec * ss1;
            float4 st = make_float4(pr0*ar0 - pi0*ai0, pr0*ai0 + pi0*ar0,
                                    pr1*ar1 - pi1*ai1, pr1*ai1 + pi1*ar1);
            *(float4*)(outp + j) = st;
        }
    }
}

// f = 512 column only
__global__ void __launch_bounds__(128) k_gemm_last(const float* __restrict__ avg_dist) {
    __shared__ float2 xs[128];
    int p = blockIdx.x, d = threadIdx.x;
    xs[d] = g_bufA[(size_t)(p*128 + d)*FP_ + 512];
    __syncthreads();
    const float* Kp = g_K + (size_t)p * D_ * D_;
    float ar = 0.0f, ai = 0.0f;
#pragma unroll 8
    for (int e = 0; e < 128; e++) {
        float kv = Kp[e*128 + d];
        float2 x = xs[e];
        ar = fmaf(kv, x.x, ar);
        ai = fmaf(kv, x.y, ai);
    }
    int row = p*128 + d;
    float dist = avg_dist[row];
    float b = c_c32() * (dist * c_s32());
    float dec = __expf(c_kdec() * dist);
    float ss, cc; sc_big(b * 512.0f, ss, cc);
    float pr = dec * cc, pi = dec * ss;
    g_bufB[(size_t)row*FP_ + 512] = make_float2(pr*ar - pi*ai, pr*ai + pi*ar);
}

// ---------------- SpMM: bufA = A @ bufB, echo += w_rec*pf_rec*bufA ------------
// edge-outer, float4 gathers (2 f per load), 8 strips of 64 f in registers.
__global__ void __launch_bounds__(256) k_spmm(const float* __restrict__ rpos,
                                              const float* __restrict__ rcpos) {
    __shared__ __align__(16) float2 esh[8][520];
    int w = threadIdx.x >> 5, lane = threadIdx.x & 31;
    int row = blockIdx.x * 8 + w;
    int s = g_rowptr[row], e = g_rowptr[row+1];

    float4 acc[8];                        // (re0,im0,re1,im1) for f = k*64+lane*2
#pragma unroll
    for (int k = 0; k < 8; k++) acc[k] = make_float4(0.f, 0.f, 0.f, 0.f);
    float ar16 = 0.0f, ai16 = 0.0f;       // f = 512 (lane 0)

    for (int j = s; j < e; j++) {
        int cj = g_cols[j];
        float vj = g_vals[j];
        const float4* __restrict__ base = (const float4*)(g_bufB + (size_t)cj * FP_);
#pragma unroll
        for (int k = 0; k < 8; k++) {
            float4 t = base[k*32 + lane];
            acc[k].x = fmaf(vj, t.x, acc[k].x);
            acc[k].y = fmaf(vj, t.y, acc[k].y);
            acc[k].z = fmaf(vj, t.z, acc[k].z);
            acc[k].w = fmaf(vj, t.w, acc[k].w);
        }
        if (lane == 0) {
            float2 t = g_bufB[(size_t)cj*FP_ + 512];
            ar16 = fmaf(vj, t.x, ar16);
            ai16 = fmaf(vj, t.y, ai16);
        }
    }

    float px = rpos[3*row+0], py = rpos[3*row+1], pz = rpos[3*row+2];
    float rx = px - rcpos[0], ry = py - rcpos[1], rz = pz - rcpos[2];
    float dr = sqrtf(rx*rx + ry*ry + rz*rz);
    float br = c_c32() * (dr * c_s32());
    float wamp = __expf(c_kdec() * dr) / (dr*dr + 0.001f);

    float4* outp = (float4*)(g_bufA + (size_t)row*FP_);
#pragma unroll
    for (int k = 0; k < 8; k++) {
        int f = k*64 + lane*2;
        outp[k*32 + lane] = acc[k];
        float s0, c0; sc_big(br * (float)f, s0, c0);
        float s1, c1; sc_big(br * (float)(f+1), s1, c1);
        float4 ev = make_float4(wamp * (c0*acc[k].x - s0*acc[k].y),
                                wamp * (c0*acc[k].y + s0*acc[k].x),
                                wamp * (c1*acc[k].z - s1*acc[k].w),
                                wamp * (c1*acc[k].w + s1*acc[k].z));
        *(float4*)&esh[w][f] = ev;
    }
    if (lane == 0) {
        g_bufA[(size_t)row*FP_ + 512] = make_float2(ar16, ai16);
        float s2, c2; sc_big(br * 512.0f, s2, c2);
        esh[w][512] = make_float2(wamp * (c2*ar16 - s2*ai16), wamp * (c2*ai16 + s2*ar16));
    }
    __syncthreads();
    for (int f = threadIdx.x; f < F_; f += 256) {
        float sr = 0.0f, si = 0.0f;
#pragma unroll
        for (int ww = 0; ww < 8; ww++) { sr += esh[ww][f].x; si += esh[ww][f].y; }
        atomicAdd(&g_echo[2*f  ], sr);
        atomicAdd(&g_echo[2*f+1], si);
    }
}

// ---------------- final: irfft(echo) / fsm_window -----------------------------
__global__ void __launch_bounds__(1024) k_ifft() {
    __shared__ float twc[T_], tws[T_];
    __shared__ float2 es[32];
    int t = threadIdx.x, b = blockIdx.x;
    {
        float th = (float)(2.0*3.14159265358979323846/1024.0) * (float)t;
        float s, c; __sincosf(th, &s, &c);
        twc[t] = c; tws[t] = s;
    }
    if (t < 32) {
        int k = b*32 + 1 + t;
        float2 v = make_float2(g_echo[2*k], g_echo[2*k+1]);
        if (k == 512) { v.x *= 0.5f; v.y *= 0.5f; }
        es[t] = v;
    }
    __syncthreads();
    float sum = 0.0f;
#pragma unroll 8
    for (int i = 0; i < 32; i++) {
        int k = b*32 + 1 + i;
        int m = (k * t) & 1023;
        float2 X = es[i];
        sum = fmaf(2.0f * X.x, twc[m], sum);
        sum = fmaf(-2.0f * X.y, tws[m], sum);
    }
    atomicAdd(&g_time[t], sum);
}

__global__ void __launch_bounds__(1024) k_scale(float* __restrict__ out) {
    int t = threadIdx.x;
    float v = (g_time[t] + g_echo[0]) * (1.0f / 1024.0f);
    float ta = (float)t / 16000.0f;
    float fsm = __expf(LOG_GAMMA_F * ta);
    out[t] = v / fsm;
}

// ---------------- launcher ----------------------------------------------------
extern "C" void kernel_launch(void* const* d_in, const int* in_sizes, int n_in,
                              void* d_out, int out_size) {
    const float* spos  = (const float*)d_in[0];
    const float* rcpos = (const float*)d_in[1];
    const float* absorb= (const float*)d_in[2];
    const float* scat  = (const float*)d_in[3];
    const float* gkv   = (const float*)d_in[4];
    const float* basis = (const float*)d_in[5];
    const float* avg   = (const float*)d_in[6];
    const float* rpos  = (const float*)d_in[7];
    const int*   gkr   = (const int*)d_in[8];
    const int*   gkc   = (const int*)d_in[9];
    const int*   obj   = (const int*)d_in[10];

    // Order chosen so launch #4 (what ncu -s captures) is the heavy k_gemm.
    k_buildKzero<<<(P_*D_*D_ + 255)/256, 256>>>(basis, absorb, scat, obj);  // 1
    k_hist<<<E_/256, 256>>>(gkr);                                           // 2
    k_rad<<<R_/8, 256>>>(rpos, spos, rcpos);                                // 3
    k_gemm<<<dim3(P_, 16), 256>>>(avg);                                     // 4  <- profile target
    k_scan<<<1, 1024>>>();                                                  // 5
    k_scatter<<<E_/256, 256>>>(gkr, gkc, gkv);                              // 6
    k_gemm_last<<<P_, 128>>>(avg);                                          // 7
    k_spmm<<<R_/8, 256>>>(rpos, rcpos);                                     // 8
    for (int b = 1; b < 4; b++) {
        k_gemm<<<dim3(P_, 16), 256>>>(avg);
        k_gemm_last<<<P_, 128>>>(avg);
        k_spmm<<<R_/8, 256>>>(rpos, rcpos);
    }
    k_ifft<<<16, 1024>>>();
    k_scale<<<1, 1024>>>((float*)d_out);
}

// round 11
// speedup vs baseline: 1.3146x; 1.3146x over previous
#include <cuda_runtime.h>
#include <cuda_bf16.h>
#include <cstdint>

#define P_  128
#define D_  128
#define R_  16384
#define E_  131072
#define T_  1024
#define F_  513
#define FP_ 520     // padded row stride in float2 (16B-aligned rows)

// ---------------- scratch (static device allocations; no cudaMalloc) ----------
static __device__ __align__(16) float2 g_bufA[R_*FP_ + 256];   // r_k
static __device__ __align__(16) float2 g_bufB[R_*FP_ + 256];   // prop * (K r)
static __device__ __align__(16) float  g_K[P_*D_*D_];          // [p][e][d] (f=512 path)
static __device__ __align__(16) uint4  g_AfragHi[P_*8*8*32];   // mma-fragment-ordered K (hi)
static __device__ __align__(16) uint4  g_AfragLo[P_*8*8*32];   // mma-fragment-ordered K (lo)
static __device__ __align__(16) int g_rowptr[R_+4];
static __device__ __align__(16) int g_rowcnt[R_];
static __device__ int    g_cols[E_];
static __device__ float  g_vals[E_];
static __device__ float  g_echo[2*F_];
static __device__ float  g_time[T_];

// ---------------- constants matching reference fp32 rounding ------------------
__device__ __forceinline__ float c_s32()  { return (float)(16000.0/343.0); }
__device__ __forceinline__ float c_c32()  { return (float)(-2.0*3.14159265358979323846/1024.0); }
__device__ __forceinline__ float c_kdec() { return (float)(-6.907755278982137/343.0 - 0.001); }
#define LOG_GAMMA_F (-6.907755278982137f)

__device__ __forceinline__ void sc_big(float x, float& s, float& c) {
    float k = rintf(x * 0.15915494309189535f);
    float r = fmaf(k, -6.28125f, x);
    r = fmaf(k, -1.9353071795864769e-3f, r);
    __sincosf(r, &s, &c);
}

__device__ __forceinline__ uint32_t smem_u32(const void* p) {
    uint32_t a;
    asm("{ .reg .u64 t; cvta.to.shared.u64 t, %1; cvt.u32.u64 %0, t; }" : "=r"(a) : "l"(p));
    return a;
}

__device__ __forceinline__ uint32_t pk_bf2(float a, float b) {
    __nv_bfloat16 ha = __float2bfloat16(a), hb = __float2bfloat16(b);
    return ((uint32_t)__bfloat16_as_ushort(hb) << 16) | __bfloat16_as_ushort(ha);
}
__device__ __forceinline__ uint32_t pk_bf2_lo(float a, float b) {
    __nv_bfloat16 ha = __float2bfloat16(a), hb = __float2bfloat16(b);
    float ra = a - __bfloat162float(ha);
    float rb = b - __bfloat162float(hb);
    __nv_bfloat16 la = __float2bfloat16(ra), lb = __float2bfloat16(rb);
    return ((uint32_t)__bfloat16_as_ushort(lb) << 16) | __bfloat16_as_ushort(la);
}

// base-ISA tensor ops (sm_80+/75+, valid in compute_103 PTX)
__device__ __forceinline__ void mma_bf16(float& d0, float& d1, float& d2, float& d3,
                                         uint32_t a0, uint32_t a1, uint32_t a2, uint32_t a3,
                                         uint32_t b0, uint32_t b1) {
    asm volatile("mma.sync.aligned.m16n8k16.row.col.f32.bf16.bf16.f32 "
                 "{%0,%1,%2,%3}, {%4,%5,%6,%7}, {%8,%9}, {%0,%1,%2,%3};"
                 : "+f"(d0), "+f"(d1), "+f"(d2), "+f"(d3)
                 : "r"(a0), "r"(a1), "r"(a2), "r"(a3), "r"(b0), "r"(b1));
}
__device__ __forceinline__ void ldsm_x4_t(uint32_t& r0, uint32_t& r1, uint32_t& r2, uint32_t& r3,
                                          uint32_t addr) {
    asm volatile("ldmatrix.sync.aligned.m8n8.x4.trans.shared.b16 {%0,%1,%2,%3}, [%4];"
                 : "=r"(r0), "=r"(r1), "=r"(r2), "=r"(r3) : "r"(addr));
}

// ---------------- setup: build K (fp32, f=512 path), zero echo/time/rowcnt ----
__global__ void k_buildKzero(const float* __restrict__ basis, const float* __restrict__ absorb,
                             const float* __restrict__ scat, const int* __restrict__ obj) {
    int idx = blockIdx.x * blockDim.x + threadIdx.x;
    if (idx < 2*F_) g_echo[idx] = 0.0f;
    if (idx < T_)   g_time[idx] = 0.0f;
    if (idx < R_)   g_rowcnt[idx] = 0;
    if (idx >= P_*D_*D_) return;
    int p = idx / (D_*D_);
    int rem = idx - p*D_*D_;
    int e = rem / D_;
    int d = rem - e*D_;
    int o = obj[p];
    float refl = 1.0f - absorb[o];
    float c0 = refl * scat[o];
    float c1 = refl * (1.0f - scat[o]);
    g_K[idx] = c0 * basis[d*D_ + e] + c1 * basis[D_*D_ + d*D_ + e];
}

// build mma-fragment-ordered bf16 hi/lo A. idx = ((p*8+s)*8+dt)*32+lane.
__global__ void k_buildA(const float* __restrict__ basis, const float* __restrict__ absorb,
                         const float* __restrict__ scat, const int* __restrict__ obj) {
    int idx = blockIdx.x * blockDim.x + threadIdx.x;    // 262144 total
    int lane = idx & 31;
    int dt = (idx >> 5) & 7;
    int s  = (idx >> 8) & 7;
    int p  = idx >> 11;
    int o = obj[p];
    float refl = 1.0f - absorb[o];
    float c0 = refl * scat[o];
    float c1 = refl * (1.0f - scat[o]);
    int r  = lane >> 2, cq = lane & 3;
    int d0 = dt*16 + r, d1 = d0 + 8;
    int k0 = s*16 + cq*2;
#define KV(d, e) (c0 * basis[(d)*D_ + (e)] + c1 * basis[D_*D_ + (d)*D_ + (e)])
    float v00 = KV(d0, k0),     v01 = KV(d0, k0+1);
    float v10 = KV(d1, k0),     v11 = KV(d1, k0+1);
    float v02 = KV(d0, k0+8),   v03 = KV(d0, k0+9);
    float v12 = KV(d1, k0+8),   v13 = KV(d1, k0+9);
#undef KV
    g_AfragHi[idx] = make_uint4(pk_bf2(v00,v01), pk_bf2(v10,v11), pk_bf2(v02,v03), pk_bf2(v12,v13));
    g_AfragLo[idx] = make_uint4(pk_bf2_lo(v00,v01), pk_bf2_lo(v10,v11),
                                pk_bf2_lo(v02,v03), pk_bf2_lo(v12,v13));
}

__global__ void k_hist(const int* __restrict__ gkr) {
    int e = blockIdx.x * blockDim.x + threadIdx.x;
    if (e < E_) atomicAdd(&g_rowcnt[gkr[e]], 1);
}

__global__ void __launch_bounds__(1024) k_scan() {
    __shared__ int wsum[32];
    int t = threadIdx.x, lane = t & 31, wid = t >> 5;
    int4 v[4];
    const int4* src = (const int4*)g_rowcnt;
#pragma unroll
    for (int i = 0; i < 4; i++) v[i] = src[t*4 + i];
    const int* x = (const int*)v;
    int loc[16], sum = 0;
#pragma unroll
    for (int i = 0; i < 16; i++) { loc[i] = sum; sum += x[i]; }
    int incl = sum;
#pragma unroll
    for (int off = 1; off < 32; off <<= 1) {
        int n = __shfl_up_sync(0xffffffffu, incl, off);
        if (lane >= off) incl += n;
    }
    if (lane == 31) wsum[wid] = incl;
    __syncthreads();
    if (wid == 0) {
        int ws = wsum[lane];
#pragma unroll
        for (int off = 1; off < 32; off <<= 1) {
            int n = __shfl_up_sync(0xffffffffu, ws, off);
            if (lane >= off) ws += n;
        }
        wsum[lane] = ws;
    }
    __syncthreads();
    int off0 = (wid > 0 ? wsum[wid-1] : 0) + (incl - sum);
    int4 o[4];
    int* op = (int*)o;
#pragma unroll
    for (int i = 0; i < 16; i++) op[i] = off0 + loc[i];
    int4* dst = (int4*)g_rowptr;
    int4* cz  = (int4*)g_rowcnt;
    int4 z = make_int4(0,0,0,0);
#pragma unroll
    for (int i = 0; i < 4; i++) { dst[t*4 + i] = o[i]; cz[t*4 + i] = z; }
    if (t == 1023) g_rowptr[R_] = wsum[31];
}

__global__ void k_scatter(const int* __restrict__ gkr, const int* __restrict__ gkc,
                          const float* __restrict__ gkv) {
    int e = blockIdx.x * blockDim.x + threadIdx.x;
    if (e >= E_) return;
    int r = gkr[e];
    int pos = g_rowptr[r] + atomicAdd(&g_rowcnt[r], 1);
    g_cols[pos] = gkc[e];
    g_vals[pos] = gkv[e];
}

// ---------------- rad: bufA = rad, echo += w_rec*pf_rec*rad -------------------
__global__ void __launch_bounds__(256) k_rad(const float* __restrict__ rpos,
                                             const float* __restrict__ spos,
                                             const float* __restrict__ rcpos) {
    __shared__ __align__(16) float2 esh[8][520];
    int w = threadIdx.x >> 5, lane = threadIdx.x & 31;
    int row = blockIdx.x * 8 + w;

    float px = rpos[3*row+0], py = rpos[3*row+1], pz = rpos[3*row+2];
    float dx = px - spos[0], dy = py - spos[1], dz = pz - spos[2];
    float ds = sqrtf(dx*dx + dy*dy + dz*dz);
    float bs = c_c32() * (ds * c_s32());
    float amp = __expf(c_kdec() * ds) / (ds*ds + 0.001f);

    float rx = px - rcpos[0], ry = py - rcpos[1], rz = pz - rcpos[2];
    float dr = sqrtf(rx*rx + ry*ry + rz*rz);
    float br = c_c32() * (dr * c_s32());
    float wamp = __expf(c_kdec() * dr) / (dr*dr + 0.001f);

#pragma unroll
    for (int k = 0; k < 16; k++) {
        int f = k*32 + lane;
        float s1, c1; sc_big(bs * (float)f, s1, c1);
        float2 rad = make_float2(amp * c1, amp * s1);
        g_bufA[(size_t)row*FP_ + f] = rad;
        float s2, c2; sc_big(br * (float)f, s2, c2);
        esh[w][f] = make_float2(wamp * (c2*rad.x - s2*rad.y), wamp * (c2*rad.y + s2*rad.x));
    }
    if (lane == 0) {
        float s1, c1; sc_big(bs * 512.0f, s1, c1);
        float2 rad = make_float2(amp * c1, amp * s1);
        g_bufA[(size_t)row*FP_ + 512] = rad;
        float s2, c2; sc_big(br * 512.0f, s2, c2);
        esh[w][512] = make_float2(wamp * (c2*rad.x - s2*rad.y), wamp * (c2*rad.y + s2*rad.x));
    }
    __syncthreads();
    for (int f = threadIdx.x; f < F_; f += 256) {
        float sr = 0.0f, si = 0.0f;
#pragma unroll
        for (int ww = 0; ww < 8; ww++) { sr += esh[ww][f].x; si += esh[ww][f].y; }
        atomicAdd(&g_echo[2*f  ], sr);
        atomicAdd(&g_echo[2*f+1], si);
    }
}

// ---------------- tensor GEMM (mma.sync bf16-split): bufB = prop*(K_p @ bufA) -
// grid (P_, 16), 256 thr. Block: D[128d x 64n] (n = re/im-interleaved, 32 cplx f).
// Warps: 4 along d x 2 along n; warp tile 32d x 32n. A from fragment-ordered
// global (hi/lo); B staged [k][n] bf16 in smem, 144B pitch, ldmatrix.x4.trans.
#define BP_ 144   // B row pitch bytes (72 bf16) — conflict-free STS.128 + ldmatrix
__global__ void __launch_bounds__(256) k_gemm_tc(const float* __restrict__ avg_dist) {
    __shared__ __align__(16) unsigned char Bhi[128*BP_];
    __shared__ __align__(16) unsigned char Blo[128*BP_];
    int p = blockIdx.x, ft = blockIdx.y, f0 = ft*32;
    int tid = threadIdx.x, w = tid >> 5, lane = tid & 31;
    int wd = w & 3, wn = w >> 2;

    // ---- stage B: thread owns (k = tid/2, half = tid&1) -> 32 n values
    {
        int k = tid >> 1, half = tid & 1;
        const float4* src = (const float4*)(g_bufA + (size_t)(p*128 + k)*FP_ + f0) + half*8;
        uint32_t hi[16], lo[16];
#pragma unroll
        for (int j = 0; j < 8; j++) {
            float4 v = src[j];
            hi[2*j]   = pk_bf2(v.x, v.y);
            hi[2*j+1] = pk_bf2(v.z, v.w);
            lo[2*j]   = pk_bf2_lo(v.x, v.y);
            lo[2*j+1] = pk_bf2_lo(v.z, v.w);
        }
        uint4* dh = (uint4*)(Bhi + k*BP_ + half*64);
        uint4* dl = (uint4*)(Blo + k*BP_ + half*64);
#pragma unroll
        for (int q = 0; q < 4; q++) {
            dh[q] = make_uint4(hi[4*q], hi[4*q+1], hi[4*q+2], hi[4*q+3]);
            dl[q] = make_uint4(lo[4*q], lo[4*q+1], lo[4*q+2], lo[4*q+3]);
        }
    }
    __syncthreads();

    float acc[2][4][4];
#pragma unroll
    for (int i = 0; i < 2; i++)
#pragma unroll
        for (int j = 0; j < 4; j++)
#pragma unroll
            for (int q = 0; q < 4; q++) acc[i][j][q] = 0.0f;

    // ldmatrix lane addresses: matrix g = lane/8 -> (k +8 if g&1, n +8 if g>>1)
    int g = lane >> 3, lr = lane & 7;
    uint32_t rowoff = (uint32_t)(((g & 1)*8 + lr) * BP_);
    uint32_t bs_hi = smem_u32(Bhi), bs_lo = smem_u32(Blo);
    uint32_t co0 = bs_hi + rowoff + (uint32_t)((wn*32 +  0 + (g >> 1)*8) * 2);
    uint32_t co1 = bs_hi + rowoff + (uint32_t)((wn*32 + 16 + (g >> 1)*8) * 2);
    uint32_t cl0 = bs_lo + rowoff + (uint32_t)((wn*32 +  0 + (g >> 1)*8) * 2);
    uint32_t cl1 = bs_lo + rowoff + (uint32_t)((wn*32 + 16 + (g >> 1)*8) * 2);

    const uint4* Ah = g_AfragHi + ((size_t)p * 8) * 8 * 32;
    const uint4* Al = g_AfragLo + ((size_t)p * 8) * 8 * 32;

#pragma unroll
    for (int s = 0; s < 8; s++) {
        uint4 ah0 = Ah[((s*8) + wd*2 + 0)*32 + lane];
        uint4 ah1 = Ah[((s*8) + wd*2 + 1)*32 + lane];
        uint4 al0 = Al[((s*8) + wd*2 + 0)*32 + lane];
        uint4 al1 = Al[((s*8) + wd*2 + 1)*32 + lane];
        uint32_t soff = (uint32_t)(s * 16 * BP_);
        uint32_t bh[8], bl[8];
        ldsm_x4_t(bh[0], bh[1], bh[2], bh[3], co0 + soff);
        ldsm_x4_t(bh[4], bh[5], bh[6], bh[7], co1 + soff);
        ldsm_x4_t(bl[0], bl[1], bl[2], bl[3], cl0 + soff);
        ldsm_x4_t(bl[4], bl[5], bl[6], bl[7], cl1 + soff);
#pragma unroll
        for (int nt = 0; nt < 4; nt++) {
            // dt = 0
            mma_bf16(acc[0][nt][0], acc[0][nt][1], acc[0][nt][2], acc[0][nt][3],
                     ah0.x, ah0.y, ah0.z, ah0.w, bh[2*nt], bh[2*nt+1]);
            mma_bf16(acc[0][nt][0], acc[0][nt][1], acc[0][nt][2], acc[0][nt][3],
                     ah0.x, ah0.y, ah0.z, ah0.w, bl[2*nt], bl[2*nt+1]);
            mma_bf16(acc[0][nt][0], acc[0][nt][1], acc[0][nt][2], acc[0][nt][3],
                     al0.x, al0.y, al0.z, al0.w, bh[2*nt], bh[2*nt+1]);
            // dt = 1
            mma_bf16(acc[1][nt][0], acc[1][nt][1], acc[1][nt][2], acc[1][nt][3],
                     ah1.x, ah1.y, ah1.z, ah1.w, bh[2*nt], bh[2*nt+1]);
            mma_bf16(acc[1][nt][0], acc[1][nt][1], acc[1][nt][2], acc[1][nt][3],
                     ah1.x, ah1.y, ah1.z, ah1.w, bl[2*nt], bl[2*nt+1]);
            mma_bf16(acc[1][nt][0], acc[1][nt][1], acc[1][nt][2], acc[1][nt][3],
                     al1.x, al1.y, al1.z, al1.w, bh[2*nt], bh[2*nt+1]);
        }
    }

    // ---- epilogue: C frag (row r=lane/4 & r+8, cols 2(lane%4),+1 = re,im of one f)
    int r0 = lane >> 2, fq = lane & 3;
#pragma unroll
    for (int dt = 0; dt < 2; dt++) {
#pragma unroll
        for (int half = 0; half < 2; half++) {
            int d = wd*32 + dt*16 + half*8 + r0;
            int row = p*128 + d;
            float dist = avg_dist[row];
            float b = c_c32() * (dist * c_s32());
            float dec = __expf(c_kdec() * dist);
            float2* outp = g_bufB + (size_t)row*FP_ + f0 + wn*16;
#pragma unroll
            for (int nt = 0; nt < 4; nt++) {
                float ar = acc[dt][nt][half*2 + 0];
                float ai = acc[dt][nt][half*2 + 1];
                int fl = nt*4 + fq;
                int f = f0 + wn*16 + fl;
                float ss, cc; sc_big(b * (float)f, ss, cc);
                float pr = dec * cc, pi = dec * ss;
                outp[fl] = make_float2(pr*ar - pi*ai, pr*ai + pi*ar);
            }
        }
    }
}

// f = 512 column only (fp32 path)
__global__ void __launch_bounds__(128) k_gemm_last(const float* __restrict__ avg_dist) {
    __shared__ float2 xs[128];
    int p = blockIdx.x, d = threadIdx.x;
    xs[d] = g_bufA[(size_t)(p*128 + d)*FP_ + 512];
    __syncthreads();
    const float* Kp = g_K + (size_t)p * D_ * D_;
    float ar = 0.0f, ai = 0.0f;
#pragma unroll 8
    for (int e = 0; e < 128; e++) {
        float kv = Kp[e*128 + d];
        float2 x = xs[e];
        ar = fmaf(kv, x.x, ar);
        ai = fmaf(kv, x.y, ai);
    }
    int row = p*128 + d;
    float dist = avg_dist[row];
    float b = c_c32() * (dist * c_s32());
    float dec = __expf(c_kdec() * dist);
    float ss, cc; sc_big(b * 512.0f, ss, cc);
    float pr = dec * cc, pi = dec * ss;
    g_bufB[(size_t)row*FP_ + 512] = make_float2(pr*ar - pi*ai, pr*ai + pi*ar);
}

// ---------------- SpMM: bufA = A @ bufB, echo += w_rec*pf_rec*bufA ------------
__global__ void __launch_bounds__(256) k_spmm(const float* __restrict__ rpos,
                                              const float* __restrict__ rcpos) {
    __shared__ __align__(16) float2 esh[8][520];
    int w = threadIdx.x >> 5, lane = threadIdx.x & 31;
    int row = blockIdx.x * 8 + w;
    int s = g_rowptr[row], e = g_rowptr[row+1];

    float4 acc[8];
#pragma unroll
    for (int k = 0; k < 8; k++) acc[k] = make_float4(0.f, 0.f, 0.f, 0.f);
    float ar16 = 0.0f, ai16 = 0.0f;

    for (int j = s; j < e; j++) {
        int cj = g_cols[j];
        float vj = g_vals[j];
        const float4* __restrict__ base = (const float4*)(g_bufB + (size_t)cj * FP_);
#pragma unroll
        for (int k = 0; k < 8; k++) {
            float4 t = base[k*32 + lane];
            acc[k].x = fmaf(vj, t.x, acc[k].x);
            acc[k].y = fmaf(vj, t.y, acc[k].y);
            acc[k].z = fmaf(vj, t.z, acc[k].z);
            acc[k].w = fmaf(vj, t.w, acc[k].w);
        }
        if (lane == 0) {
            float2 t = g_bufB[(size_t)cj*FP_ + 512];
            ar16 = fmaf(vj, t.x, ar16);
            ai16 = fmaf(vj, t.y, ai16);
        }
    }

    float px = rpos[3*row+0], py = rpos[3*row+1], pz = rpos[3*row+2];
    float rx = px - rcpos[0], ry = py - rcpos[1], rz = pz - rcpos[2];
    float dr = sqrtf(rx*rx + ry*ry + rz*rz);
    float br = c_c32() * (dr * c_s32());
    float wamp = __expf(c_kdec() * dr) / (dr*dr + 0.001f);

    float4* outp = (float4*)(g_bufA + (size_t)row*FP_);
#pragma unroll
    for (int k = 0; k < 8; k++) {
        int f = k*64 + lane*2;
        outp[k*32 + lane] = acc[k];
        float s0, c0; sc_big(br * (float)f, s0, c0);
        float s1, c1; sc_big(br * (float)(f+1), s1, c1);
        float4 ev = make_float4(wamp * (c0*acc[k].x - s0*acc[k].y),
                                wamp * (c0*acc[k].y + s0*acc[k].x),
                                wamp * (c1*acc[k].z - s1*acc[k].w),
                                wamp * (c1*acc[k].w + s1*acc[k].z));
        *(float4*)&esh[w][f] = ev;
    }
    if (lane == 0) {
        g_bufA[(size_t)row*FP_ + 512] = make_float2(ar16, ai16);
        float s2, c2; sc_big(br * 512.0f, s2, c2);
        esh[w][512] = make_float2(wamp * (c2*ar16 - s2*ai16), wamp * (c2*ai16 + s2*ar16));
    }
    __syncthreads();
    for (int f = threadIdx.x; f < F_; f += 256) {
        float sr = 0.0f, si = 0.0f;
#pragma unroll
        for (int ww = 0; ww < 8; ww++) { sr += esh[ww][f].x; si += esh[ww][f].y; }
        atomicAdd(&g_echo[2*f  ], sr);
        atomicAdd(&g_echo[2*f+1], si);
    }
}

// ---------------- final: irfft(echo) / fsm_window -----------------------------
__global__ void __launch_bounds__(1024) k_ifft() {
    __shared__ float twc[T_], tws[T_];
    __shared__ float2 es[32];
    int t = threadIdx.x, b = blockIdx.x;
    {
        float th = (float)(2.0*3.14159265358979323846/1024.0) * (float)t;
        float s, c; __sincosf(th, &s, &c);
        twc[t] = c; tws[t] = s;
    }
    if (t < 32) {
        int k = b*32 + 1 + t;
        float2 v = make_float2(g_echo[2*k], g_echo[2*k+1]);
        if (k == 512) { v.x *= 0.5f; v.y *= 0.5f; }
        es[t] = v;
    }
    __syncthreads();
    float sum = 0.0f;
#pragma unroll 8
    for (int i = 0; i < 32; i++) {
        int k = b*32 + 1 + i;
        int m = (k * t) & 1023;
        float2 X = es[i];
        sum = fmaf(2.0f * X.x, twc[m], sum);
        sum = fmaf(-2.0f * X.y, tws[m], sum);
    }
    atomicAdd(&g_time[t], sum);
}

__global__ void __launch_bounds__(1024) k_scale(float* __restrict__ out) {
    int t = threadIdx.x;
    float v = (g_time[t] + g_echo[0]) * (1.0f / 1024.0f);
    float ta = (float)t / 16000.0f;
    float fsm = __expf(LOG_GAMMA_F * ta);
    out[t] = v / fsm;
}

// ---------------- launcher ----------------------------------------------------
extern "C" void kernel_launch(void* const* d_in, const int* in_sizes, int n_in,
                              void* d_out, int out_size) {
    const float* spos  = (const float*)d_in[0];
    const float* rcpos = (const float*)d_in[1];
    const float* absorb= (const float*)d_in[2];
    const float* scat  = (const float*)d_in[3];
    const float* gkv   = (const float*)d_in[4];
    const float* basis = (const float*)d_in[5];
    const float* avg   = (const float*)d_in[6];
    const float* rpos  = (const float*)d_in[7];
    const int*   gkr   = (const int*)d_in[8];
    const int*   gkc   = (const int*)d_in[9];
    const int*   obj   = (const int*)d_in[10];

    // Launch #4 (ncu -s 5 -c 1 target) = first k_gemm_tc.
    k_buildKzero<<<(P_*D_*D_ + 255)/256, 256>>>(basis, absorb, scat, obj);  // 1
    k_buildA<<<(P_*8*8*32)/256, 256>>>(basis, absorb, scat, obj);           // 2
    k_rad<<<R_/8, 256>>>(rpos, spos, rcpos);                                // 3
    k_gemm_tc<<<dim3(P_, 16), 256>>>(avg);                                  // 4  <- profile target
    k_hist<<<E_/256, 256>>>(gkr);                                           // 5
    k_scan<<<1, 1024>>>();                                                  // 6
    k_scatter<<<E_/256, 256>>>(gkr, gkc, gkv);                              // 7
    k_gemm_last<<<P_, 128>>>(avg);                                          // 8
    k_spmm<<<R_/8, 256>>>(rpos, rcpos);                                     // 9
    for (int b = 1; b < 4; b++) {
        k_gemm_tc<<<dim3(P_, 16), 256>>>(avg);
        k_gemm_last<<<P_, 128>>>(avg);
        k_spmm<<<R_/8, 256>>>(rpos, rcpos);
    }
    k_ifft<<<16, 1024>>>();
    k_scale<<<1, 1024>>>((float*)d_out);
}

// round 12
// speedup vs baseline: 1.3412x; 1.0202x over previous
#include <cuda_runtime.h>
#include <cuda_bf16.h>
#include <cstdint>

#define P_  128
#define D_  128
#define R_  16384
#define E_  131072
#define T_  1024
#define F_  513
#define FP_ 520     // padded row stride in float2 (16B-aligned rows)

// ---------------- scratch (static device allocations; no cudaMalloc) ----------
static __device__ __align__(16) float2 g_bufA[R_*FP_ + 256];   // r_k
static __device__ __align__(16) float2 g_bufB[R_*FP_ + 256];   // prop * (K r)
static __device__ __align__(16) float  g_K[P_*D_*D_];          // [p][e][d] (f=512 path)
static __device__ __align__(16) uint4  g_AfragHi[P_*8*8*32];   // mma-fragment-ordered K (hi)
static __device__ __align__(16) uint4  g_AfragLo[P_*8*8*32];   // mma-fragment-ordered K (lo)
static __device__ __align__(16) int g_rowptr[R_+4];
static __device__ __align__(16) int g_rowcnt[R_];
static __device__ int    g_cols[E_];
static __device__ float  g_vals[E_];
static __device__ float  g_echo[2*F_];
static __device__ float  g_time[T_];

// ---------------- constants matching reference fp32 rounding ------------------
__device__ __forceinline__ float c_s32()  { return (float)(16000.0/343.0); }
__device__ __forceinline__ float c_c32()  { return (float)(-2.0*3.14159265358979323846/1024.0); }
__device__ __forceinline__ float c_kdec() { return (float)(-6.907755278982137/343.0 - 0.001); }
#define LOG_GAMMA_F (-6.907755278982137f)

__device__ __forceinline__ void sc_big(float x, float& s, float& c) {
    float k = rintf(x * 0.15915494309189535f);
    float r = fmaf(k, -6.28125f, x);
    r = fmaf(k, -1.9353071795864769e-3f, r);
    __sincosf(r, &s, &c);
}

__device__ __forceinline__ uint32_t smem_u32(const void* p) {
    uint32_t a;
    asm("{ .reg .u64 t; cvta.to.shared.u64 t, %1; cvt.u32.u64 %0, t; }" : "=r"(a) : "l"(p));
    return a;
}

__device__ __forceinline__ uint32_t pk_bf2(float a, float b) {
    __nv_bfloat16 ha = __float2bfloat16(a), hb = __float2bfloat16(b);
    return ((uint32_t)__bfloat16_as_ushort(hb) << 16) | __bfloat16_as_ushort(ha);
}
__device__ __forceinline__ uint32_t pk_bf2_lo(float a, float b) {
    __nv_bfloat16 ha = __float2bfloat16(a), hb = __float2bfloat16(b);
    float ra = a - __bfloat162float(ha);
    float rb = b - __bfloat162float(hb);
    __nv_bfloat16 la = __float2bfloat16(ra), lb = __float2bfloat16(rb);
    return ((uint32_t)__bfloat16_as_ushort(lb) << 16) | __bfloat16_as_ushort(la);
}

// base-ISA tensor ops (sm_80+/75+, valid in compute_103 PTX)
__device__ __forceinline__ void mma_bf16(float& d0, float& d1, float& d2, float& d3,
                                         uint32_t a0, uint32_t a1, uint32_t a2, uint32_t a3,
                                         uint32_t b0, uint32_t b1) {
    asm volatile("mma.sync.aligned.m16n8k16.row.col.f32.bf16.bf16.f32 "
                 "{%0,%1,%2,%3}, {%4,%5,%6,%7}, {%8,%9}, {%0,%1,%2,%3};"
                 : "+f"(d0), "+f"(d1), "+f"(d2), "+f"(d3)
                 : "r"(a0), "r"(a1), "r"(a2), "r"(a3), "r"(b0), "r"(b1));
}
__device__ __forceinline__ void ldsm_x4_t(uint32_t& r0, uint32_t& r1, uint32_t& r2, uint32_t& r3,
                                          uint32_t addr) {
    asm volatile("ldmatrix.sync.aligned.m8n8.x4.trans.shared.b16 {%0,%1,%2,%3}, [%4];"
                 : "=r"(r0), "=r"(r1), "=r"(r2), "=r"(r3) : "r"(addr));
}

// ---------------- setup: build K (fp32, f=512 path), zero echo/time/rowcnt ----
__global__ void k_buildKzero(const float* __restrict__ basis, const float* __restrict__ absorb,
                             const float* __restrict__ scat, const int* __restrict__ obj) {
    int idx = blockIdx.x * blockDim.x + threadIdx.x;
    if (idx < 2*F_) g_echo[idx] = 0.0f;
    if (idx < T_)   g_time[idx] = 0.0f;
    if (idx < R_)   g_rowcnt[idx] = 0;
    if (idx >= P_*D_*D_) return;
    int p = idx / (D_*D_);
    int rem = idx - p*D_*D_;
    int e = rem / D_;
    int d = rem - e*D_;
    int o = obj[p];
    float refl = 1.0f - absorb[o];
    float c0 = refl * scat[o];
    float c1 = refl * (1.0f - scat[o]);
    g_K[idx] = c0 * basis[d*D_ + e] + c1 * basis[D_*D_ + d*D_ + e];
}

// build mma-fragment-ordered bf16 hi/lo A. idx = ((p*8+s)*8+dt)*32+lane.
__global__ void k_buildA(const float* __restrict__ basis, const float* __restrict__ absorb,
                         const float* __restrict__ scat, const int* __restrict__ obj) {
    int idx = blockIdx.x * blockDim.x + threadIdx.x;    // 262144 total
    int lane = idx & 31;
    int dt = (idx >> 5) & 7;
    int s  = (idx >> 8) & 7;
    int p  = idx >> 11;
    int o = obj[p];
    float refl = 1.0f - absorb[o];
    float c0 = refl * scat[o];
    float c1 = refl * (1.0f - scat[o]);
    int r  = lane >> 2, cq = lane & 3;
    int d0 = dt*16 + r, d1 = d0 + 8;
    int k0 = s*16 + cq*2;
#define KV(d, e) (c0 * basis[(d)*D_ + (e)] + c1 * basis[D_*D_ + (d)*D_ + (e)])
    float v00 = KV(d0, k0),     v01 = KV(d0, k0+1);
    float v10 = KV(d1, k0),     v11 = KV(d1, k0+1);
    float v02 = KV(d0, k0+8),   v03 = KV(d0, k0+9);
    float v12 = KV(d1, k0+8),   v13 = KV(d1, k0+9);
#undef KV
    g_AfragHi[idx] = make_uint4(pk_bf2(v00,v01), pk_bf2(v10,v11), pk_bf2(v02,v03), pk_bf2(v12,v13));
    g_AfragLo[idx] = make_uint4(pk_bf2_lo(v00,v01), pk_bf2_lo(v10,v11),
                                pk_bf2_lo(v02,v03), pk_bf2_lo(v12,v13));
}

__global__ void k_hist(const int* __restrict__ gkr) {
    int e = blockIdx.x * blockDim.x + threadIdx.x;
    if (e < E_) atomicAdd(&g_rowcnt[gkr[e]], 1);
}

__global__ void __launch_bounds__(1024) k_scan() {
    __shared__ int wsum[32];
    int t = threadIdx.x, lane = t & 31, wid = t >> 5;
    int4 v[4];
    const int4* src = (const int4*)g_rowcnt;
#pragma unroll
    for (int i = 0; i < 4; i++) v[i] = src[t*4 + i];
    const int* x = (const int*)v;
    int loc[16], sum = 0;
#pragma unroll
    for (int i = 0; i < 16; i++) { loc[i] = sum; sum += x[i]; }
    int incl = sum;
#pragma unroll
    for (int off = 1; off < 32; off <<= 1) {
        int n = __shfl_up_sync(0xffffffffu, incl, off);
        if (lane >= off) incl += n;
    }
    if (lane == 31) wsum[wid] = incl;
    __syncthreads();
    if (wid == 0) {
        int ws = wsum[lane];
#pragma unroll
        for (int off = 1; off < 32; off <<= 1) {
            int n = __shfl_up_sync(0xffffffffu, ws, off);
            if (lane >= off) ws += n;
        }
        wsum[lane] = ws;
    }
    __syncthreads();
    int off0 = (wid > 0 ? wsum[wid-1] : 0) + (incl - sum);
    int4 o[4];
    int* op = (int*)o;
#pragma unroll
    for (int i = 0; i < 16; i++) op[i] = off0 + loc[i];
    int4* dst = (int4*)g_rowptr;
    int4* cz  = (int4*)g_rowcnt;
    int4 z = make_int4(0,0,0,0);
#pragma unroll
    for (int i = 0; i < 4; i++) { dst[t*4 + i] = o[i]; cz[t*4 + i] = z; }
    if (t == 1023) g_rowptr[R_] = wsum[31];
}

__global__ void k_scatter(const int* __restrict__ gkr, const int* __restrict__ gkc,
                          const float* __restrict__ gkv) {
    int e = blockIdx.x * blockDim.x + threadIdx.x;
    if (e >= E_) return;
    int r = gkr[e];
    int pos = g_rowptr[r] + atomicAdd(&g_rowcnt[r], 1);
    g_cols[pos] = gkc[e];
    g_vals[pos] = gkv[e];
}

// ---------------- rad: bufA = rad, echo += w_rec*pf_rec*rad -------------------
__global__ void __launch_bounds__(256) k_rad(const float* __restrict__ rpos,
                                             const float* __restrict__ spos,
                                             const float* __restrict__ rcpos) {
    __shared__ __align__(16) float2 esh[8][520];
    int w = threadIdx.x >> 5, lane = threadIdx.x & 31;
    int row = blockIdx.x * 8 + w;

    float px = rpos[3*row+0], py = rpos[3*row+1], pz = rpos[3*row+2];
    float dx = px - spos[0], dy = py - spos[1], dz = pz - spos[2];
    float ds = sqrtf(dx*dx + dy*dy + dz*dz);
    float bs = c_c32() * (ds * c_s32());
    float amp = __expf(c_kdec() * ds) / (ds*ds + 0.001f);

    float rx = px - rcpos[0], ry = py - rcpos[1], rz = pz - rcpos[2];
    float dr = sqrtf(rx*rx + ry*ry + rz*rz);
    float br = c_c32() * (dr * c_s32());
    float wamp = __expf(c_kdec() * dr) / (dr*dr + 0.001f);

#pragma unroll
    for (int k = 0; k < 16; k++) {
        int f = k*32 + lane;
        float s1, c1; sc_big(bs * (float)f, s1, c1);
        float2 rad = make_float2(amp * c1, amp * s1);
        g_bufA[(size_t)row*FP_ + f] = rad;
        float s2, c2; sc_big(br * (float)f, s2, c2);
        esh[w][f] = make_float2(wamp * (c2*rad.x - s2*rad.y), wamp * (c2*rad.y + s2*rad.x));
    }
    if (lane == 0) {
        float s1, c1; sc_big(bs * 512.0f, s1, c1);
        float2 rad = make_float2(amp * c1, amp * s1);
        g_bufA[(size_t)row*FP_ + 512] = rad;
        float s2, c2; sc_big(br * 512.0f, s2, c2);
        esh[w][512] = make_float2(wamp * (c2*rad.x - s2*rad.y), wamp * (c2*rad.y + s2*rad.x));
    }
    __syncthreads();
    for (int f = threadIdx.x; f < F_; f += 256) {
        float sr = 0.0f, si = 0.0f;
#pragma unroll
        for (int ww = 0; ww < 8; ww++) { sr += esh[ww][f].x; si += esh[ww][f].y; }
        atomicAdd(&g_echo[2*f  ], sr);
        atomicAdd(&g_echo[2*f+1], si);
    }
}

// ---------------- tensor GEMM (mma.sync bf16-split): bufB = prop*(K_p @ bufA) -
// grid (P_, 16), 512 thr, 2 blocks/SM (32 warps). Block: D[128d x 64n].
// Warps: 8 along d x 2 along n; warp tile 16d x 32n. acc = 16 floats/thread.
#define BP_ 144   // B row pitch bytes (72 bf16) — conflict-free STS.128 + ldmatrix
__global__ void __launch_bounds__(512, 2) k_gemm_tc(const float* __restrict__ avg_dist) {
    __shared__ __align__(16) unsigned char Bhi[128*BP_];
    __shared__ __align__(16) unsigned char Blo[128*BP_];
    int p = blockIdx.x, ft = blockIdx.y, f0 = ft*32;
    int tid = threadIdx.x, w = tid >> 5, lane = tid & 31;
    int wd = w & 7, wn = w >> 3;

    // ---- stage B: thread owns (k = tid/4, quarter = tid&3) -> 16 n values
    {
        int k = tid >> 2, q = tid & 3;
        const float4* src = (const float4*)(g_bufA + (size_t)(p*128 + k)*FP_ + f0) + q*4;
        uint32_t hi[8], lo[8];
#pragma unroll
        for (int j = 0; j < 4; j++) {
            float4 v = src[j];
            hi[2*j]   = pk_bf2(v.x, v.y);
            hi[2*j+1] = pk_bf2(v.z, v.w);
            lo[2*j]   = pk_bf2_lo(v.x, v.y);
            lo[2*j+1] = pk_bf2_lo(v.z, v.w);
        }
        uint4* dh = (uint4*)(Bhi + k*BP_ + q*32);
        uint4* dl = (uint4*)(Blo + k*BP_ + q*32);
        dh[0] = make_uint4(hi[0], hi[1], hi[2], hi[3]);
        dh[1] = make_uint4(hi[4], hi[5], hi[6], hi[7]);
        dl[0] = make_uint4(lo[0], lo[1], lo[2], lo[3]);
        dl[1] = make_uint4(lo[4], lo[5], lo[6], lo[7]);
    }
    __syncthreads();

    float acc[4][4];
#pragma unroll
    for (int j = 0; j < 4; j++)
#pragma unroll
        for (int q = 0; q < 4; q++) acc[j][q] = 0.0f;

    // ldmatrix lane addresses: matrix g = lane/8 -> (k +8 if g&1, n +8 if g>>1)
    int g = lane >> 3, lr = lane & 7;
    uint32_t rowoff = (uint32_t)(((g & 1)*8 + lr) * BP_);
    uint32_t bs_hi = smem_u32(Bhi), bs_lo = smem_u32(Blo);
    uint32_t co0 = bs_hi + rowoff + (uint32_t)((wn*32 +  0 + (g >> 1)*8) * 2);
    uint32_t co1 = bs_hi + rowoff + (uint32_t)((wn*32 + 16 + (g >> 1)*8) * 2);
    uint32_t cl0 = bs_lo + rowoff + (uint32_t)((wn*32 +  0 + (g >> 1)*8) * 2);
    uint32_t cl1 = bs_lo + rowoff + (uint32_t)((wn*32 + 16 + (g >> 1)*8) * 2);

    const uint4* Ah = g_AfragHi + ((size_t)p * 8) * 8 * 32;
    const uint4* Al = g_AfragLo + ((size_t)p * 8) * 8 * 32;

#pragma unroll
    for (int s = 0; s < 8; s++) {
        uint4 ah = Ah[((s*8) + wd)*32 + lane];
        uint4 al = Al[((s*8) + wd)*32 + lane];
        uint32_t soff = (uint32_t)(s * 16 * BP_);
        uint32_t bh[8], bl[8];
        ldsm_x4_t(bh[0], bh[1], bh[2], bh[3], co0 + soff);
        ldsm_x4_t(bh[4], bh[5], bh[6], bh[7], co1 + soff);
        ldsm_x4_t(bl[0], bl[1], bl[2], bl[3], cl0 + soff);
        ldsm_x4_t(bl[4], bl[5], bl[6], bl[7], cl1 + soff);
#pragma unroll
        for (int nt = 0; nt < 4; nt++) {
            mma_bf16(acc[nt][0], acc[nt][1], acc[nt][2], acc[nt][3],
                     ah.x, ah.y, ah.z, ah.w, bh[2*nt], bh[2*nt+1]);
            mma_bf16(acc[nt][0], acc[nt][1], acc[nt][2], acc[nt][3],
                     ah.x, ah.y, ah.z, ah.w, bl[2*nt], bl[2*nt+1]);
            mma_bf16(acc[nt][0], acc[nt][1], acc[nt][2], acc[nt][3],
                     al.x, al.y, al.z, al.w, bh[2*nt], bh[2*nt+1]);
        }
    }

    // ---- epilogue: C frag (rows r0 & r0+8, cols 2fq,2fq+1 = re,im of one f)
    int r0 = lane >> 2, fq = lane & 3;
#pragma unroll
    for (int half = 0; half < 2; half++) {
        int d = wd*16 + half*8 + r0;
        int row = p*128 + d;
        float dist = avg_dist[row];
        float b = c_c32() * (dist * c_s32());
        float dec = __expf(c_kdec() * dist);
        float2* outp = g_bufB + (size_t)row*FP_ + f0 + wn*16;
#pragma unroll
        for (int nt = 0; nt < 4; nt++) {
            float ar = acc[nt][half*2 + 0];
            float ai = acc[nt][half*2 + 1];
            int fl = nt*4 + fq;
            int f = f0 + wn*16 + fl;
            float ss, cc; sc_big(b * (float)f, ss, cc);
            float pr = dec * cc, pi = dec * ss;
            outp[fl] = make_float2(pr*ar - pi*ai, pr*ai + pi*ar);
        }
    }
}

// f = 512 column only (fp32 path)
__global__ void __launch_bounds__(128) k_gemm_last(const float* __restrict__ avg_dist) {
    __shared__ float2 xs[128];
    int p = blockIdx.x, d = threadIdx.x;
    xs[d] = g_bufA[(size_t)(p*128 + d)*FP_ + 512];
    __syncthreads();
    const float* Kp = g_K + (size_t)p * D_ * D_;
    float ar = 0.0f, ai = 0.0f;
#pragma unroll 8
    for (int e = 0; e < 128; e++) {
        float kv = Kp[e*128 + d];
        float2 x = xs[e];
        ar = fmaf(kv, x.x, ar);
        ai = fmaf(kv, x.y, ai);
    }
    int row = p*128 + d;
    float dist = avg_dist[row];
    float b = c_c32() * (dist * c_s32());
    float dec = __expf(c_kdec() * dist);
    float ss, cc; sc_big(b * 512.0f, ss, cc);
    float pr = dec * cc, pi = dec * ss;
    g_bufB[(size_t)row*FP_ + 512] = make_float2(pr*ar - pi*ai, pr*ai + pi*ar);
}

// ---------------- SpMM: bufA = A @ bufB, echo += w_rec*pf_rec*bufA ------------
__global__ void __launch_bounds__(256) k_spmm(const float* __restrict__ rpos,
                                              const float* __restrict__ rcpos) {
    __shared__ __align__(16) float2 esh[8][520];
    int w = threadIdx.x >> 5, lane = threadIdx.x & 31;
    int row = blockIdx.x * 8 + w;
    int s = g_rowptr[row], e = g_rowptr[row+1];

    float4 acc[8];
#pragma unroll
    for (int k = 0; k < 8; k++) acc[k] = make_float4(0.f, 0.f, 0.f, 0.f);
    float ar16 = 0.0f, ai16 = 0.0f;

    for (int j = s; j < e; j++) {
        int cj = g_cols[j];
        float vj = g_vals[j];
        const float4* __restrict__ base = (const float4*)(g_bufB + (size_t)cj * FP_);
#pragma unroll
        for (int k = 0; k < 8; k++) {
            float4 t = base[k*32 + lane];
            acc[k].x = fmaf(vj, t.x, acc[k].x);
            acc[k].y = fmaf(vj, t.y, acc[k].y);
            acc[k].z = fmaf(vj, t.z, acc[k].z);
            acc[k].w = fmaf(vj, t.w, acc[k].w);
        }
        if (lane == 0) {
            float2 t = g_bufB[(size_t)cj*FP_ + 512];
            ar16 = fmaf(vj, t.x, ar16);
            ai16 = fmaf(vj, t.y, ai16);
        }
    }

    float px = rpos[3*row+0], py = rpos[3*row+1], pz = rpos[3*row+2];
    float rx = px - rcpos[0], ry = py - rcpos[1], rz = pz - rcpos[2];
    float dr = sqrtf(rx*rx + ry*ry + rz*rz);
    float br = c_c32() * (dr * c_s32());
    float wamp = __expf(c_kdec() * dr) / (dr*dr + 0.001f);

    float4* outp = (float4*)(g_bufA + (size_t)row*FP_);
#pragma unroll
    for (int k = 0; k < 8; k++) {
        int f = k*64 + lane*2;
        outp[k*32 + lane] = acc[k];
        float s0, c0; sc_big(br * (float)f, s0, c0);
        float s1, c1; sc_big(br * (float)(f+1), s1, c1);
        float4 ev = make_float4(wamp * (c0*acc[k].x - s0*acc[k].y),
                                wamp * (c0*acc[k].y + s0*acc[k].x),
                                wamp * (c1*acc[k].z - s1*acc[k].w),
                                wamp * (c1*acc[k].w + s1*acc[k].z));
        *(float4*)&esh[w][f] = ev;
    }
    if (lane == 0) {
        g_bufA[(size_t)row*FP_ + 512] = make_float2(ar16, ai16);
        float s2, c2; sc_big(br * 512.0f, s2, c2);
        esh[w][512] = make_float2(wamp * (c2*ar16 - s2*ai16), wamp * (c2*ai16 + s2*ar16));
    }
    __syncthreads();
    for (int f = threadIdx.x; f < F_; f += 256) {
        float sr = 0.0f, si = 0.0f;
#pragma unroll
        for (int ww = 0; ww < 8; ww++) { sr += esh[ww][f].x; si += esh[ww][f].y; }
        atomicAdd(&g_echo[2*f  ], sr);
        atomicAdd(&g_echo[2*f+1], si);
    }
}

// ---------------- final: irfft(echo) / fsm_window -----------------------------
__global__ void __launch_bounds__(1024) k_ifft() {
    __shared__ float twc[T_], tws[T_];
    __shared__ float2 es[32];
    int t = threadIdx.x, b = blockIdx.x;
    {
        float th = (float)(2.0*3.14159265358979323846/1024.0) * (float)t;
        float s, c; __sincosf(th, &s, &c);
        twc[t] = c; tws[t] = s;
    }
    if (t < 32) {
        int k = b*32 + 1 + t;
        float2 v = make_float2(g_echo[2*k], g_echo[2*k+1]);
        if (k == 512) { v.x *= 0.5f; v.y *= 0.5f; }
        es[t] = v;
    }
    __syncthreads();
    float sum = 0.0f;
#pragma unroll 8
    for (int i = 0; i < 32; i++) {
        int k = b*32 + 1 + i;
        int m = (k * t) & 1023;
        float2 X = es[i];
        sum = fmaf(2.0f * X.x, twc[m], sum);
        sum = fmaf(-2.0f * X.y, tws[m], sum);
    }
    atomicAdd(&g_time[t], sum);
}

__global__ void __launch_bounds__(1024) k_scale(float* __restrict__ out) {
    int t = threadIdx.x;
    float v = (g_time[t] + g_echo[0]) * (1.0f / 1024.0f);
    float ta = (float)t / 16000.0f;
    float fsm = __expf(LOG_GAMMA_F * ta);
    out[t] = v / fsm;
}

// ---------------- launcher ----------------------------------------------------
extern "C" void kernel_launch(void* const* d_in, const int* in_sizes, int n_in,
                              void* d_out, int out_size) {
    const float* spos  = (const float*)d_in[0];
    const float* rcpos = (const float*)d_in[1];
    const float* absorb= (const float*)d_in[2];
    const float* scat  = (const float*)d_in[3];
    const float* gkv   = (const float*)d_in[4];
    const float* basis = (const float*)d_in[5];
    const float* avg   = (const float*)d_in[6];
    const float* rpos  = (const float*)d_in[7];
    const int*   gkr   = (const int*)d_in[8];
    const int*   gkc   = (const int*)d_in[9];
    const int*   obj   = (const int*)d_in[10];

    // Launch #4 (ncu -s 5 -c 1 target) = first k_gemm_tc.
    k_buildKzero<<<(P_*D_*D_ + 255)/256, 256>>>(basis, absorb, scat, obj);  // 1
    k_buildA<<<(P_*8*8*32)/256, 256>>>(basis, absorb, scat, obj);           // 2
    k_rad<<<R_/8, 256>>>(rpos, spos, rcpos);                                // 3
    k_gemm_tc<<<dim3(P_, 16), 512>>>(avg);                                  // 4  <- profile target
    k_hist<<<E_/256, 256>>>(gkr);                                           // 5
    k_scan<<<1, 1024>>>();                                                  // 6
    k_scatter<<<E_/256, 256>>>(gkr, gkc, gkv);                              // 7
    k_gemm_last<<<P_, 128>>>(avg);                                          // 8
    k_spmm<<<R_/8, 256>>>(rpos, rcpos);                                     // 9
    for (int b = 1; b < 4; b++) {
        k_gemm_tc<<<dim3(P_, 16), 512>>>(avg);
        k_gemm_last<<<P_, 128>>>(avg);
        k_spmm<<<R_/8, 256>>>(rpos, rcpos);
    }
    k_ifft<<<16, 1024>>>();
    k_scale<<<1, 1024>>>((float*)d_out);
}

// round 13
// speedup vs baseline: 1.3627x; 1.0160x over previous
#include <cuda_runtime.h>
#include <cuda_bf16.h>
#include <cstdint>

#define P_  128
#define D_  128
#define R_  16384
#define E_  131072
#define T_  1024
#define F_  513
#define FP_ 520     // padded row stride in float2 (16B-aligned rows)

// ---------------- scratch (static device allocations; no cudaMalloc) ----------
static __device__ __align__(16) float2 g_bufA[R_*FP_ + 256];   // r_k
static __device__ __align__(16) float2 g_bufB[R_*FP_ + 256];   // prop * (K r)
static __device__ __align__(16) float  g_K[P_*D_*D_];          // [p][e][d] (f=512 path)
static __device__ __align__(16) uint4  g_AfragHi[P_*8*8*32];   // mma-fragment-ordered K (hi)
static __device__ __align__(16) uint4  g_AfragLo[P_*8*8*32];   // mma-fragment-ordered K (lo)
static __device__ __align__(16) int g_rowptr[R_+4];
static __device__ __align__(16) int g_rowcnt[R_];
static __device__ int    g_cols[E_];
static __device__ float  g_vals[E_];
static __device__ float  g_echo[2*F_];
static __device__ float  g_time[T_];

// ---------------- constants matching reference fp32 rounding ------------------
__device__ __forceinline__ float c_s32()  { return (float)(16000.0/343.0); }
__device__ __forceinline__ float c_c32()  { return (float)(-2.0*3.14159265358979323846/1024.0); }
__device__ __forceinline__ float c_kdec() { return (float)(-6.907755278982137/343.0 - 0.001); }
#define LOG_GAMMA_F (-6.907755278982137f)

__device__ __forceinline__ void sc_big(float x, float& s, float& c) {
    float k = rintf(x * 0.15915494309189535f);
    float r = fmaf(k, -6.28125f, x);
    r = fmaf(k, -1.9353071795864769e-3f, r);
    __sincosf(r, &s, &c);
}

__device__ __forceinline__ float2 cmul(float2 a, float2 b) {
    return make_float2(a.x*b.x - a.y*b.y, a.x*b.y + a.y*b.x);
}

__device__ __forceinline__ uint32_t smem_u32(const void* p) {
    uint32_t a;
    asm("{ .reg .u64 t; cvta.to.shared.u64 t, %1; cvt.u32.u64 %0, t; }" : "=r"(a) : "l"(p));
    return a;
}

__device__ __forceinline__ uint32_t pk_bf2(float a, float b) {
    __nv_bfloat16 ha = __float2bfloat16(a), hb = __float2bfloat16(b);
    return ((uint32_t)__bfloat16_as_ushort(hb) << 16) | __bfloat16_as_ushort(ha);
}
__device__ __forceinline__ uint32_t pk_bf2_lo(float a, float b) {
    __nv_bfloat16 ha = __float2bfloat16(a), hb = __float2bfloat16(b);
    float ra = a - __bfloat162float(ha);
    float rb = b - __bfloat162float(hb);
    __nv_bfloat16 la = __float2bfloat16(ra), lb = __float2bfloat16(rb);
    return ((uint32_t)__bfloat16_as_ushort(lb) << 16) | __bfloat16_as_ushort(la);
}

// base-ISA tensor ops (sm_80+/75+, valid in compute_103 PTX)
__device__ __forceinline__ void mma_bf16(float& d0, float& d1, float& d2, float& d3,
                                         uint32_t a0, uint32_t a1, uint32_t a2, uint32_t a3,
                                         uint32_t b0, uint32_t b1) {
    asm volatile("mma.sync.aligned.m16n8k16.row.col.f32.bf16.bf16.f32 "
                 "{%0,%1,%2,%3}, {%4,%5,%6,%7}, {%8,%9}, {%0,%1,%2,%3};"
                 : "+f"(d0), "+f"(d1), "+f"(d2), "+f"(d3)
                 : "r"(a0), "r"(a1), "r"(a2), "r"(a3), "r"(b0), "r"(b1));
}
__device__ __forceinline__ void ldsm_x4_t(uint32_t& r0, uint32_t& r1, uint32_t& r2, uint32_t& r3,
                                          uint32_t addr) {
    asm volatile("ldmatrix.sync.aligned.m8n8.x4.trans.shared.b16 {%0,%1,%2,%3}, [%4];"
                 : "=r"(r0), "=r"(r1), "=r"(r2), "=r"(r3) : "r"(addr));
}

// ---------------- setup: build K (fp32, f=512 path), zero echo/time/rowcnt ----
__global__ void k_buildKzero(const float* __restrict__ basis, const float* __restrict__ absorb,
                             const float* __restrict__ scat, const int* __restrict__ obj) {
    int idx = blockIdx.x * blockDim.x + threadIdx.x;
    if (idx < 2*F_) g_echo[idx] = 0.0f;
    if (idx < T_)   g_time[idx] = 0.0f;
    if (idx < R_)   g_rowcnt[idx] = 0;
    if (idx >= P_*D_*D_) return;
    int p = idx / (D_*D_);
    int rem = idx - p*D_*D_;
    int e = rem / D_;
    int d = rem - e*D_;
    int o = obj[p];
    float refl = 1.0f - absorb[o];
    float c0 = refl * scat[o];
    float c1 = refl * (1.0f - scat[o]);
    g_K[idx] = c0 * basis[d*D_ + e] + c1 * basis[D_*D_ + d*D_ + e];
}

// build mma-fragment-ordered bf16 hi/lo A. idx = ((p*8+s)*8+dt)*32+lane.
__global__ void k_buildA(const float* __restrict__ basis, const float* __restrict__ absorb,
                         const float* __restrict__ scat, const int* __restrict__ obj) {
    int idx = blockIdx.x * blockDim.x + threadIdx.x;    // 262144 total
    int lane = idx & 31;
    int dt = (idx >> 5) & 7;
    int s  = (idx >> 8) & 7;
    int p  = idx >> 11;
    int o = obj[p];
    float refl = 1.0f - absorb[o];
    float c0 = refl * scat[o];
    float c1 = refl * (1.0f - scat[o]);
    int r  = lane >> 2, cq = lane & 3;
    int d0 = dt*16 + r, d1 = d0 + 8;
    int k0 = s*16 + cq*2;
#define KV(d, e) (c0 * basis[(d)*D_ + (e)] + c1 * basis[D_*D_ + (d)*D_ + (e)])
    float v00 = KV(d0, k0),     v01 = KV(d0, k0+1);
    float v10 = KV(d1, k0),     v11 = KV(d1, k0+1);
    float v02 = KV(d0, k0+8),   v03 = KV(d0, k0+9);
    float v12 = KV(d1, k0+8),   v13 = KV(d1, k0+9);
#undef KV
    g_AfragHi[idx] = make_uint4(pk_bf2(v00,v01), pk_bf2(v10,v11), pk_bf2(v02,v03), pk_bf2(v12,v13));
    g_AfragLo[idx] = make_uint4(pk_bf2_lo(v00,v01), pk_bf2_lo(v10,v11),
                                pk_bf2_lo(v02,v03), pk_bf2_lo(v12,v13));
}

__global__ void k_hist(const int* __restrict__ gkr) {
    int e = blockIdx.x * blockDim.x + threadIdx.x;
    if (e < E_) atomicAdd(&g_rowcnt[gkr[e]], 1);
}

__global__ void __launch_bounds__(1024) k_scan() {
    __shared__ int wsum[32];
    int t = threadIdx.x, lane = t & 31, wid = t >> 5;
    int4 v[4];
    const int4* src = (const int4*)g_rowcnt;
#pragma unroll
    for (int i = 0; i < 4; i++) v[i] = src[t*4 + i];
    const int* x = (const int*)v;
    int loc[16], sum = 0;
#pragma unroll
    for (int i = 0; i < 16; i++) { loc[i] = sum; sum += x[i]; }
    int incl = sum;
#pragma unroll
    for (int off = 1; off < 32; off <<= 1) {
        int n = __shfl_up_sync(0xffffffffu, incl, off);
        if (lane >= off) incl += n;
    }
    if (lane == 31) wsum[wid] = incl;
    __syncthreads();
    if (wid == 0) {
        int ws = wsum[lane];
#pragma unroll
        for (int off = 1; off < 32; off <<= 1) {
            int n = __shfl_up_sync(0xffffffffu, ws, off);
            if (lane >= off) ws += n;
        }
        wsum[lane] = ws;
    }
    __syncthreads();
    int off0 = (wid > 0 ? wsum[wid-1] : 0) + (incl - sum);
    int4 o[4];
    int* op = (int*)o;
#pragma unroll
    for (int i = 0; i < 16; i++) op[i] = off0 + loc[i];
    int4* dst = (int4*)g_rowptr;
    int4* cz  = (int4*)g_rowcnt;
    int4 z = make_int4(0,0,0,0);
#pragma unroll
    for (int i = 0; i < 4; i++) { dst[t*4 + i] = o[i]; cz[t*4 + i] = z; }
    if (t == 1023) g_rowptr[R_] = wsum[31];
}

__global__ void k_scatter(const int* __restrict__ gkr, const int* __restrict__ gkc,
                          const float* __restrict__ gkv) {
    int e = blockIdx.x * blockDim.x + threadIdx.x;
    if (e >= E_) return;
    int r = gkr[e];
    int pos = g_rowptr[r] + atomicAdd(&g_rowcnt[r], 1);
    g_cols[pos] = gkc[e];
    g_vals[pos] = gkv[e];
}

// ---------------- rad: bufA = rad, echo += w_rec*pf_rec*rad -------------------
// phase recurrence: per lane 4 seed sincos; step = f-stride 32.
__global__ void __launch_bounds__(256) k_rad(const float* __restrict__ rpos,
                                             const float* __restrict__ spos,
                                             const float* __restrict__ rcpos) {
    __shared__ __align__(16) float2 esh[8][520];
    int w = threadIdx.x >> 5, lane = threadIdx.x & 31;
    int row = blockIdx.x * 8 + w;

    float px = rpos[3*row+0], py = rpos[3*row+1], pz = rpos[3*row+2];
    float dx = px - spos[0], dy = py - spos[1], dz = pz - spos[2];
    float ds = sqrtf(dx*dx + dy*dy + dz*dz);
    float bs = c_c32() * (ds * c_s32());
    float amp = __expf(c_kdec() * ds) / (ds*ds + 0.001f);

    float rx = px - rcpos[0], ry = py - rcpos[1], rz = pz - rcpos[2];
    float dr = sqrtf(rx*rx + ry*ry + rz*rz);
    float br = c_c32() * (dr * c_s32());
    float wamp = __expf(c_kdec() * dr) / (dr*dr + 0.001f);

    float s0, c0;
    sc_big(bs * (float)lane, s0, c0);
    float2 wsrc = make_float2(c0, s0);
    sc_big(bs * 32.0f, s0, c0);
    float2 wsstep = make_float2(c0, s0);
    sc_big(br * (float)lane, s0, c0);
    float2 wrec = make_float2(c0, s0);
    sc_big(br * 32.0f, s0, c0);
    float2 wrstep = make_float2(c0, s0);

#pragma unroll
    for (int k = 0; k < 16; k++) {
        int f = k*32 + lane;
        float2 rad = make_float2(amp * wsrc.x, amp * wsrc.y);
        g_bufA[(size_t)row*FP_ + f] = rad;
        float2 er = cmul(rad, wrec);
        esh[w][f] = make_float2(wamp * er.x, wamp * er.y);
        wsrc = cmul(wsrc, wsstep);
        wrec = cmul(wrec, wrstep);
    }
    // after 16 steps: wsrc = e^{i bs (lane+512)}, wrec likewise -> lane 0 = f 512
    if (lane == 0) {
        float2 rad = make_float2(amp * wsrc.x, amp * wsrc.y);
        g_bufA[(size_t)row*FP_ + 512] = rad;
        float2 er = cmul(rad, wrec);
        esh[w][512] = make_float2(wamp * er.x, wamp * er.y);
    }
    __syncthreads();
    for (int f = threadIdx.x; f < F_; f += 256) {
        float sr = 0.0f, si = 0.0f;
#pragma unroll
        for (int ww = 0; ww < 8; ww++) { sr += esh[ww][f].x; si += esh[ww][f].y; }
        atomicAdd(&g_echo[2*f  ], sr);
        atomicAdd(&g_echo[2*f+1], si);
    }
}

// ---------------- tensor GEMM (mma.sync bf16-split): bufB = prop*(K_p @ bufA) -
// grid (P_, 16), 512 thr, 2 blocks/SM (32 warps). Block: D[128d x 64n].
// Warps: 8 along d x 2 along n; warp tile 16d x 32n. acc = 16 floats/thread.
#define BP_ 144   // B row pitch bytes (72 bf16) — conflict-free STS.128 + ldmatrix
__global__ void __launch_bounds__(512, 2) k_gemm_tc(const float* __restrict__ avg_dist) {
    __shared__ __align__(16) unsigned char Bhi[128*BP_];
    __shared__ __align__(16) unsigned char Blo[128*BP_];
    int p = blockIdx.x, ft = blockIdx.y, f0 = ft*32;
    int tid = threadIdx.x, w = tid >> 5, lane = tid & 31;
    int wd = w & 7, wn = w >> 3;

    // ---- stage B: thread owns (k = tid/4, quarter = tid&3) -> 16 n values
    {
        int k = tid >> 2, q = tid & 3;
        const float4* src = (const float4*)(g_bufA + (size_t)(p*128 + k)*FP_ + f0) + q*4;
        uint32_t hi[8], lo[8];
#pragma unroll
        for (int j = 0; j < 4; j++) {
            float4 v = src[j];
            hi[2*j]   = pk_bf2(v.x, v.y);
            hi[2*j+1] = pk_bf2(v.z, v.w);
            lo[2*j]   = pk_bf2_lo(v.x, v.y);
            lo[2*j+1] = pk_bf2_lo(v.z, v.w);
        }
        uint4* dh = (uint4*)(Bhi + k*BP_ + q*32);
        uint4* dl = (uint4*)(Blo + k*BP_ + q*32);
        dh[0] = make_uint4(hi[0], hi[1], hi[2], hi[3]);
        dh[1] = make_uint4(hi[4], hi[5], hi[6], hi[7]);
        dl[0] = make_uint4(lo[0], lo[1], lo[2], lo[3]);
        dl[1] = make_uint4(lo[4], lo[5], lo[6], lo[7]);
    }
    __syncthreads();

    float acc[4][4];
#pragma unroll
    for (int j = 0; j < 4; j++)
#pragma unroll
        for (int q = 0; q < 4; q++) acc[j][q] = 0.0f;

    // ldmatrix lane addresses: matrix g = lane/8 -> (k +8 if g&1, n +8 if g>>1)
    int g = lane >> 3, lr = lane & 7;
    uint32_t rowoff = (uint32_t)(((g & 1)*8 + lr) * BP_);
    uint32_t bs_hi = smem_u32(Bhi), bs_lo = smem_u32(Blo);
    uint32_t co0 = bs_hi + rowoff + (uint32_t)((wn*32 +  0 + (g >> 1)*8) * 2);
    uint32_t co1 = bs_hi + rowoff + (uint32_t)((wn*32 + 16 + (g >> 1)*8) * 2);
    uint32_t cl0 = bs_lo + rowoff + (uint32_t)((wn*32 +  0 + (g >> 1)*8) * 2);
    uint32_t cl1 = bs_lo + rowoff + (uint32_t)((wn*32 + 16 + (g >> 1)*8) * 2);

    const uint4* Ah = g_AfragHi + ((size_t)p * 8) * 8 * 32;
    const uint4* Al = g_AfragLo + ((size_t)p * 8) * 8 * 32;

#pragma unroll
    for (int s = 0; s < 8; s++) {
        uint4 ah = Ah[((s*8) + wd)*32 + lane];
        uint4 al = Al[((s*8) + wd)*32 + lane];
        uint32_t soff = (uint32_t)(s * 16 * BP_);
        uint32_t bh[8], bl[8];
        ldsm_x4_t(bh[0], bh[1], bh[2], bh[3], co0 + soff);
        ldsm_x4_t(bh[4], bh[5], bh[6], bh[7], co1 + soff);
        ldsm_x4_t(bl[0], bl[1], bl[2], bl[3], cl0 + soff);
        ldsm_x4_t(bl[4], bl[5], bl[6], bl[7], cl1 + soff);
#pragma unroll
        for (int nt = 0; nt < 4; nt++) {
            mma_bf16(acc[nt][0], acc[nt][1], acc[nt][2], acc[nt][3],
                     ah.x, ah.y, ah.z, ah.w, bh[2*nt], bh[2*nt+1]);
            mma_bf16(acc[nt][0], acc[nt][1], acc[nt][2], acc[nt][3],
                     ah.x, ah.y, ah.z, ah.w, bl[2*nt], bl[2*nt+1]);
            mma_bf16(acc[nt][0], acc[nt][1], acc[nt][2], acc[nt][3],
                     al.x, al.y, al.z, al.w, bh[2*nt], bh[2*nt+1]);
        }
    }

    // ---- epilogue with phase recurrence (stride 4 in f per nt step)
    int r0 = lane >> 2, fq = lane & 3;
#pragma unroll
    for (int half = 0; half < 2; half++) {
        int d = wd*16 + half*8 + r0;
        int row = p*128 + d;
        float dist = avg_dist[row];
        float b = c_c32() * (dist * c_s32());
        float dec = __expf(c_kdec() * dist);
        float2* outp = g_bufB + (size_t)row*FP_ + f0 + wn*16;
        int fbase = f0 + wn*16 + fq;
        float ss, cc;
        sc_big(b * (float)fbase, ss, cc);
        float2 wp = make_float2(dec * cc, dec * ss);
        sc_big(b * 4.0f, ss, cc);
        float2 wst = make_float2(cc, ss);
#pragma unroll
        for (int nt = 0; nt < 4; nt++) {
            float2 v = cmul(make_float2(acc[nt][half*2 + 0], acc[nt][half*2 + 1]), wp);
            outp[nt*4 + fq] = v;
            wp = cmul(wp, wst);
        }
    }
}

// f = 512 column only (fp32 path)
__global__ void __launch_bounds__(128) k_gemm_last(const float* __restrict__ avg_dist) {
    __shared__ float2 xs[128];
    int p = blockIdx.x, d = threadIdx.x;
    xs[d] = g_bufA[(size_t)(p*128 + d)*FP_ + 512];
    __syncthreads();
    const float* Kp = g_K + (size_t)p * D_ * D_;
    float ar = 0.0f, ai = 0.0f;
#pragma unroll 8
    for (int e = 0; e < 128; e++) {
        float kv = Kp[e*128 + d];
        float2 x = xs[e];
        ar = fmaf(kv, x.x, ar);
        ai = fmaf(kv, x.y, ai);
    }
    int row = p*128 + d;
    float dist = avg_dist[row];
    float b = c_c32() * (dist * c_s32());
    float dec = __expf(c_kdec() * dist);
    float ss, cc; sc_big(b * 512.0f, ss, cc);
    float pr = dec * cc, pi = dec * ss;
    g_bufB[(size_t)row*FP_ + 512] = make_float2(pr*ar - pi*ai, pr*ai + pi*ar);
}

// ---------------- SpMM: bufA = A @ bufB, echo += w_rec*pf_rec*bufA ------------
// edge-outer float4 gathers; echo epilogue uses phase recurrence (stride 64).
__global__ void __launch_bounds__(256) k_spmm(const float* __restrict__ rpos,
                                              const float* __restrict__ rcpos) {
    __shared__ __align__(16) float2 esh[8][520];
    int w = threadIdx.x >> 5, lane = threadIdx.x & 31;
    int row = blockIdx.x * 8 + w;
    int s = g_rowptr[row], e = g_rowptr[row+1];

    float4 acc[8];
#pragma unroll
    for (int k = 0; k < 8; k++) acc[k] = make_float4(0.f, 0.f, 0.f, 0.f);
    float ar16 = 0.0f, ai16 = 0.0f;

    for (int j = s; j < e; j++) {
        int cj = g_cols[j];
        float vj = g_vals[j];
        const float4* __restrict__ base = (const float4*)(g_bufB + (size_t)cj * FP_);
#pragma unroll
        for (int k = 0; k < 8; k++) {
            float4 t = base[k*32 + lane];
            acc[k].x = fmaf(vj, t.x, acc[k].x);
            acc[k].y = fmaf(vj, t.y, acc[k].y);
            acc[k].z = fmaf(vj, t.z, acc[k].z);
            acc[k].w = fmaf(vj, t.w, acc[k].w);
        }
        if (lane == 0) {
            float2 t = g_bufB[(size_t)cj*FP_ + 512];
            ar16 = fmaf(vj, t.x, ar16);
            ai16 = fmaf(vj, t.y, ai16);
        }
    }

    float px = rpos[3*row+0], py = rpos[3*row+1], pz = rpos[3*row+2];
    float rx = px - rcpos[0], ry = py - rcpos[1], rz = pz - rcpos[2];
    float dr = sqrtf(rx*rx + ry*ry + rz*rz);
    float br = c_c32() * (dr * c_s32());
    float wamp = __expf(c_kdec() * dr) / (dr*dr + 0.001f);

    float sx, cx;
    sc_big(br * (float)(lane*2), sx, cx);
    float2 w0 = make_float2(cx, sx);
    sc_big(br * (float)(lane*2 + 1), sx, cx);
    float2 w1 = make_float2(cx, sx);
    sc_big(br * 64.0f, sx, cx);
    float2 wst = make_float2(cx, sx);

    float4* outp = (float4*)(g_bufA + (size_t)row*FP_);
#pragma unroll
    for (int k = 0; k < 8; k++) {
        int f = k*64 + lane*2;
        outp[k*32 + lane] = acc[k];
        float2 e0 = cmul(make_float2(acc[k].x, acc[k].y), w0);
        float2 e1 = cmul(make_float2(acc[k].z, acc[k].w), w1);
        *(float4*)&esh[w][f] = make_float4(wamp*e0.x, wamp*e0.y, wamp*e1.x, wamp*e1.y);
        w0 = cmul(w0, wst);
        w1 = cmul(w1, wst);
    }
    // after 8 steps: w0 = e^{i br (lane*2 + 512)} -> lane 0 = f 512
    if (lane == 0) {
        g_bufA[(size_t)row*FP_ + 512] = make_float2(ar16, ai16);
        float2 e0 = cmul(make_float2(ar16, ai16), w0);
        esh[w][512] = make_float2(wamp*e0.x, wamp*e0.y);
    }
    __syncthreads();
    for (int f = threadIdx.x; f < F_; f += 256) {
        float sr = 0.0f, si = 0.0f;
#pragma unroll
        for (int ww = 0; ww < 8; ww++) { sr += esh[ww][f].x; si += esh[ww][f].y; }
        atomicAdd(&g_echo[2*f  ], sr);
        atomicAdd(&g_echo[2*f+1], si);
    }
}

// ---------------- final: irfft(echo) / fsm_window -----------------------------
__global__ void __launch_bounds__(1024) k_ifft() {
    __shared__ float twc[T_], tws[T_];
    __shared__ float2 es[32];
    int t = threadIdx.x, b = blockIdx.x;
    {
        float th = (float)(2.0*3.14159265358979323846/1024.0) * (float)t;
        float s, c; __sincosf(th, &s, &c);
        twc[t] = c; tws[t] = s;
    }
    if (t < 32) {
        int k = b*32 + 1 + t;
        float2 v = make_float2(g_echo[2*k], g_echo[2*k+1]);
        if (k == 512) { v.x *= 0.5f; v.y *= 0.5f; }
        es[t] = v;
    }
    __syncthreads();
    float sum = 0.0f;
#pragma unroll 8
    for (int i = 0; i < 32; i++) {
        int k = b*32 + 1 + i;
        int m = (k * t) & 1023;
        float2 X = es[i];
        sum = fmaf(2.0f * X.x, twc[m], sum);
        sum = fmaf(-2.0f * X.y, tws[m], sum);
    }
    atomicAdd(&g_time[t], sum);
}

__global__ void __launch_bounds__(1024) k_scale(float* __restrict__ out) {
    int t = threadIdx.x;
    float v = (g_time[t] + g_echo[0]) * (1.0f / 1024.0f);
    float ta = (float)t / 16000.0f;
    float fsm = __expf(LOG_GAMMA_F * ta);
    out[t] = v / fsm;
}

// ---------------- launcher ----------------------------------------------------
extern "C" void kernel_launch(void* const* d_in, const int* in_sizes, int n_in,
                              void* d_out, int out_size) {
    const float* spos  = (const float*)d_in[0];
    const float* rcpos = (const float*)d_in[1];
    const float* absorb= (const float*)d_in[2];
    const float* scat  = (const float*)d_in[3];
    const float* gkv   = (const float*)d_in[4];
    const float* basis = (const float*)d_in[5];
    const float* avg   = (const float*)d_in[6];
    const float* rpos  = (const float*)d_in[7];
    const int*   gkr   = (const int*)d_in[8];
    const int*   gkc   = (const int*)d_in[9];
    const int*   obj   = (const int*)d_in[10];

    // Launch #4 (ncu capture target) = first k_gemm_tc.
    k_buildKzero<<<(P_*D_*D_ + 255)/256, 256>>>(basis, absorb, scat, obj);  // 1
    k_buildA<<<(P_*8*8*32)/256, 256>>>(basis, absorb, scat, obj);           // 2
    k_rad<<<R_/8, 256>>>(rpos, spos, rcpos);                                // 3
    k_gemm_tc<<<dim3(P_, 16), 512>>>(avg);                                  // 4  <- profile target
    k_hist<<<E_/256, 256>>>(gkr);                                           // 5
    k_scan<<<1, 1024>>>();                                                  // 6
    k_scatter<<<E_/256, 256>>>(gkr, gkc, gkv);                              // 7
    k_gemm_last<<<P_, 128>>>(avg);                                          // 8
    k_spmm<<<R_/8, 256>>>(rpos, rcpos);                                     // 9
    for (int b = 1; b < 4; b++) {
        k_gemm_tc<<<dim3(P_, 16), 512>>>(avg);
        k_gemm_last<<<P_, 128>>>(avg);
        k_spmm<<<R_/8, 256>>>(rpos, rcpos);
    }
    k_ifft<<<16, 1024>>>();
    k_scale<<<1, 1024>>>((float*)d_out);
}